// round 6
// baseline (speedup 1.0000x reference)
#include <cuda_runtime.h>
#include <math.h>

#define TT 128   // sequence length
#define DMM 32   // model dim
#define RS 36    // padded row stride (floats) for k/v/q smem

typedef unsigned long long u64;
typedef ulonglong2 u64x2;

// ---- packed fp32x2 primitives ----
__device__ __forceinline__ u64 fma2(u64 a, u64 b, u64 c) {
    u64 d; asm("fma.rn.f32x2 %0, %1, %2, %3;" : "=l"(d) : "l"(a), "l"(b), "l"(c)); return d;
}
__device__ __forceinline__ u64 add2(u64 a, u64 b) {
    u64 d; asm("add.rn.f32x2 %0, %1, %2;" : "=l"(d) : "l"(a), "l"(b)); return d;
}
__device__ __forceinline__ u64 mul2(u64 a, u64 b) {
    u64 d; asm("mul.rn.f32x2 %0, %1, %2;" : "=l"(d) : "l"(a), "l"(b)); return d;
}
__device__ __forceinline__ u64 pack2(float lo, float hi) {
    u64 r; asm("mov.b64 %0, {%1, %2};" : "=l"(r) : "f"(lo), "f"(hi)); return r;
}
__device__ __forceinline__ float2 unpk(u64 v) {
    float2 f; asm("mov.b64 {%0, %1}, %2;" : "=f"(f.x), "=f"(f.y) : "l"(v)); return f;
}
__device__ __forceinline__ u64 rep2(float x) { return pack2(x, x); }

// ---- dynamic smem layout (float offsets) ----
// persistent: wo | bo b2 g1 be1 g2 be2 | b1
#define OFF_WO   0
#define OFF_BO   1024
#define OFF_B2   1056
#define OFF_G1   1088
#define OFF_BE1  1120
#define OFF_G2   1152
#define OFF_BE2  1184
#define OFF_B1   1216
#define OFF_U    1344
// phase A (qkv + attention):
#define OFF_KS0  (OFF_U + 0)
#define OFF_VS0  (OFF_U + 4608)
#define OFF_KS1  (OFF_U + 9216)
#define OFF_VS1  (OFF_U + 13824)
#define OFF_WQ   (OFF_U + 18432)
#define OFF_WK   (OFF_U + 19456)
#define OFF_WV   (OFF_U + 20480)
#define OFF_QS1  (OFF_U + 21504)            // parked q for batch1 (128*RS)
#define SM_FLOATS (OFF_U + 21504 + TT * RS)
// phase B (FFN), overlays phase A:
#define OFF_W1T  (OFF_U + 0)
#define OFF_W2   (OFF_U + 4096)

// dual matvec: acc{0,1}[p] = cols(2p,2p+1) of xn{0,1}(1x32) @ w(32x32)
__device__ __forceinline__ void matvec_dual(const float* __restrict__ w,
                                            const float (&x0)[32], const float (&x1)[32],
                                            u64 (&a0)[16], u64 (&a1)[16]) {
#pragma unroll
    for (int p = 0; p < 16; p++) { a0[p] = 0ull; a1[p] = 0ull; }
#pragma unroll
    for (int d = 0; d < 32; d++) {
        u64 r0 = rep2(x0[d]), r1 = rep2(x1[d]);
        const u64x2* row = reinterpret_cast<const u64x2*>(w + d * 32);
#pragma unroll
        for (int p = 0; p < 8; p++) {
            u64x2 wv = row[p];
            a0[2*p]   = fma2(r0, wv.x, a0[2*p]);
            a0[2*p+1] = fma2(r0, wv.y, a0[2*p+1]);
            a1[2*p]   = fma2(r1, wv.x, a1[2*p]);
            a1[2*p+1] = fma2(r1, wv.y, a1[2*p+1]);
        }
    }
}

__device__ __forceinline__ void store_pairs(float* dst, const u64 (&a)[16]) {
    u64x2* d2 = reinterpret_cast<u64x2*>(dst);
#pragma unroll
    for (int p = 0; p < 8; p++) d2[p] = make_ulonglong2(a[2*p], a[2*p+1]);
}

__device__ __forceinline__ void ln32(float (&v)[32], const float* g, const float* be) {
    float mu = 0.0f;
#pragma unroll
    for (int i = 0; i < 32; i++) mu += v[i];
    mu *= (1.0f / 32.0f);
    float var = 0.0f;
#pragma unroll
    for (int i = 0; i < 32; i++) { float d = v[i] - mu; var = fmaf(d, d, var); }
    var *= (1.0f / 32.0f);
    float rstd = rsqrtf(var + 1e-5f);
#pragma unroll
    for (int i = 0; i < 32; i++) v[i] = fmaf((v[i] - mu) * rstd, g[i], be[i]);
}

// single-batch causal attention, both heads in f32x2 pairs (interleaved-head layout)
// at[] out in standard order at[h*16+c]
__device__ __forceinline__ void attn_one(const float* __restrict__ ksb,
                                         const float* __restrict__ vsb,
                                         const u64 (&qp)[16], int t, float (&at)[32]) {
    u64 av[16];
#pragma unroll
    for (int c = 0; c < 16; c++) av[c] = 0ull;
    float l0 = 0.0f, l1 = 0.0f;
#pragma unroll 2
    for (int si = 0; si <= t; si++) {
        const u64x2* kr = reinterpret_cast<const u64x2*>(ksb + si * RS);
        u64 s0 = 0ull, s1 = 0ull, s2 = 0ull, s3 = 0ull;
#pragma unroll
        for (int p = 0; p < 4; p++) {
            u64x2 ka = kr[2*p], kb = kr[2*p+1];
            s0 = fma2(qp[4*p+0], ka.x, s0); s1 = fma2(qp[4*p+1], ka.y, s1);
            s2 = fma2(qp[4*p+2], kb.x, s2); s3 = fma2(qp[4*p+3], kb.y, s3);
        }
        float2 ss = unpk(add2(add2(s0, s1), add2(s2, s3)));  // (score_h0, score_h1)
        float p0 = __expf(ss.x), p1 = __expf(ss.y);          // |score| <~ 8: no max-sub
        l0 += p0; l1 += p1;
        u64 pp = pack2(p0, p1);
        const u64x2* vr = reinterpret_cast<const u64x2*>(vsb + si * RS);
#pragma unroll
        for (int p = 0; p < 8; p++) {
            u64x2 vv = vr[p];
            av[2*p]   = fma2(pp, vv.x, av[2*p]);
            av[2*p+1] = fma2(pp, vv.y, av[2*p+1]);
        }
    }
    u64 iv = pack2(__fdividef(1.0f, l0), __fdividef(1.0f, l1));
#pragma unroll
    for (int c = 0; c < 16; c++) {
        float2 a = unpk(mul2(av[c], iv));
        at[c] = a.x; at[16 + c] = a.y;
    }
}

__global__ void __launch_bounds__(128, 2) block_fused(
    const float* __restrict__ x,
    const float* __restrict__ Wq, const float* __restrict__ Wk, const float* __restrict__ Wv,
    const float* __restrict__ Wo, const float* __restrict__ bo,
    const float* __restrict__ W1, const float* __restrict__ b1,
    const float* __restrict__ W2, const float* __restrict__ b2,
    const float* __restrict__ g1, const float* __restrict__ be1,
    const float* __restrict__ g2, const float* __restrict__ be2,
    float* __restrict__ out)
{
    extern __shared__ float sm[];
    const int tid = threadIdx.x;
    const int t = tid;
    const int b0 = 2 * blockIdx.x, b1b = 2 * blockIdx.x + 1;

    // early x loads for both tokens
    const float4* xr0 = reinterpret_cast<const float4*>(x + ((size_t)b0 * TT + t) * DMM);
    const float4* xr1 = reinterpret_cast<const float4*>(x + ((size_t)b1b * TT + t) * DMM);
    float4 xv0[8], xv1[8];
#pragma unroll
    for (int i = 0; i < 8; i++) { xv0[i] = xr0[i]; xv1[i] = xr1[i]; }

    // ---- stage phase-A weights ----
    for (int i = tid; i < 1024; i += 128) {
        int d = i >> 5, j = i & 31;
        int kk = j >> 1, h = j & 1;            // interleaved-head columns: j = 2*kk + h
        int src = h * 512 + d * 16 + kk;
        sm[OFF_WQ + i] = Wq[src];
        sm[OFF_WK + i] = Wk[src];
        sm[OFF_WV + i] = Wv[src];
        sm[OFF_WO + i] = Wo[i];
    }
    if (tid < 32) {
        sm[OFF_BO  + tid] = bo[tid];  sm[OFF_B2  + tid] = b2[tid];
        sm[OFF_G1  + tid] = g1[tid];  sm[OFF_BE1 + tid] = be1[tid];
        sm[OFF_G2  + tid] = g2[tid];  sm[OFF_BE2 + tid] = be2[tid];
    }
    sm[OFF_B1 + tid] = b1[tid];
    __syncthreads();

    // ---- LN1 for both tokens ----
    float xn0[32], xn1[32];
#pragma unroll
    for (int i = 0; i < 8; i++) {
        xn0[4*i+0] = xv0[i].x; xn0[4*i+1] = xv0[i].y; xn0[4*i+2] = xv0[i].z; xn0[4*i+3] = xv0[i].w;
        xn1[4*i+0] = xv1[i].x; xn1[4*i+1] = xv1[i].y; xn1[4*i+2] = xv1[i].z; xn1[4*i+3] = xv1[i].w;
    }
    ln32(xn0, sm + OFF_G1, sm + OFF_BE1);
    ln32(xn1, sm + OFF_G1, sm + OFF_BE1);

    // ---- q,k,v projections (dual): k,v -> smem; q0 regs, q1 parked in smem ----
    u64 qp0[16];
    {
        u64 a0[16], a1[16];
        matvec_dual(sm + OFF_WK, xn0, xn1, a0, a1);
        store_pairs(sm + OFF_KS0 + t * RS, a0);
        store_pairs(sm + OFF_KS1 + t * RS, a1);
        matvec_dual(sm + OFF_WV, xn0, xn1, a0, a1);
        store_pairs(sm + OFF_VS0 + t * RS, a0);
        store_pairs(sm + OFF_VS1 + t * RS, a1);
        matvec_dual(sm + OFF_WQ, xn0, xn1, qp0, a1);
        store_pairs(sm + OFF_QS1 + t * RS, a1);   // park q(batch1), own row: no sync needed
    }
    __syncthreads();

    // ---- attention batch0 (only qp0+av live) ----
    float at0[32];
    attn_one(sm + OFF_KS0, sm + OFF_VS0, qp0, t, at0);

    // ---- reload q1, attention batch1 (at0 held, qp0 dead) ----
    float at1[32];
    {
        u64 qp1[16];
        const u64x2* q2 = reinterpret_cast<const u64x2*>(sm + OFF_QS1 + t * RS);
#pragma unroll
        for (int p = 0; p < 8; p++) { u64x2 v = q2[p]; qp1[2*p] = v.x; qp1[2*p+1] = v.y; }
        attn_one(sm + OFF_KS1, sm + OFF_VS1, qp1, t, at1);
    }

    // ---- output projection + residual (dual) ----
    float z0[32], z1[32];
    {
        u64 o0[16], o1[16];
#pragma unroll
        for (int p = 0; p < 16; p++) { o0[p] = 0ull; o1[p] = 0ull; }
#pragma unroll
        for (int j = 0; j < 32; j++) {
            u64 a0 = rep2(at0[j]), a1 = rep2(at1[j]);
            const u64x2* row = reinterpret_cast<const u64x2*>(sm + OFF_WO + j * 32);
#pragma unroll
            for (int p = 0; p < 8; p++) {
                u64x2 wv = row[p];
                o0[2*p]   = fma2(a0, wv.x, o0[2*p]);
                o0[2*p+1] = fma2(a0, wv.y, o0[2*p+1]);
                o1[2*p]   = fma2(a1, wv.x, o1[2*p]);
                o1[2*p+1] = fma2(a1, wv.y, o1[2*p+1]);
            }
        }
#pragma unroll
        for (int p = 0; p < 16; p++) {
            float2 a = unpk(o0[p]);
            z0[2*p]   = xn0[2*p]   + a.x + sm[OFF_BO + 2*p];
            z0[2*p+1] = xn0[2*p+1] + a.y + sm[OFF_BO + 2*p+1];
            float2 b = unpk(o1[p]);
            z1[2*p]   = xn1[2*p]   + b.x + sm[OFF_BO + 2*p];
            z1[2*p+1] = xn1[2*p+1] + b.y + sm[OFF_BO + 2*p+1];
        }
    }

    // ---- LN2 ----
    ln32(z0, sm + OFF_G2, sm + OFF_BE2);
    ln32(z1, sm + OFF_G2, sm + OFF_BE2);

    // ---- restage FFN weights into the union region ----
    __syncthreads();   // everyone done with ks/vs/wq/wk/wv
    for (int i = tid; i < 4096; i += 128) {
        int j = i >> 5, d = i & 31;
        sm[OFF_W1T + i] = W1[d * 128 + j];        // transpose
        sm[OFF_W2  + i] = W2[i];
    }
    __syncthreads();

    // ---- fused FFN (dual) ----
    u64 zp0[16], zp1[16], oa0[16], oa1[16];
#pragma unroll
    for (int p = 0; p < 16; p++) {
        u64 bb = pack2(sm[OFF_B2 + 2*p], sm[OFF_B2 + 2*p+1]);
        zp0[p] = pack2(z0[2*p], z0[2*p+1]);  oa0[p] = add2(zp0[p], bb);
        zp1[p] = pack2(z1[2*p], z1[2*p+1]);  oa1[p] = add2(zp1[p], bb);
    }
    for (int j = 0; j < 128; j++) {
        const u64x2* w1r = reinterpret_cast<const u64x2*>(sm + OFF_W1T + j * 32);
        u64 h0 = 0ull, h1 = 0ull, h2 = 0ull, h3 = 0ull;
        u64 g0 = 0ull, g1r = 0ull, g2r = 0ull, g3 = 0ull;
#pragma unroll
        for (int p = 0; p < 4; p++) {
            u64x2 wa = w1r[2*p], wb = w1r[2*p+1];
            h0 = fma2(zp0[4*p+0], wa.x, h0); h1 = fma2(zp0[4*p+1], wa.y, h1);
            h2 = fma2(zp0[4*p+2], wb.x, h2); h3 = fma2(zp0[4*p+3], wb.y, h3);
            g0 = fma2(zp1[4*p+0], wa.x, g0); g1r = fma2(zp1[4*p+1], wa.y, g1r);
            g2r = fma2(zp1[4*p+2], wb.x, g2r); g3 = fma2(zp1[4*p+3], wb.y, g3);
        }
        float bj = sm[OFF_B1 + j];
        float2 ha = unpk(add2(add2(h0, h1), add2(h2, h3)));
        float2 hb = unpk(add2(add2(g0, g1r), add2(g2r, g3)));
        float hj0 = fmaxf(ha.x + ha.y + bj, 0.0f);
        float hj1 = fmaxf(hb.x + hb.y + bj, 0.0f);
        u64 r0 = rep2(hj0), r1 = rep2(hj1);
        const u64x2* w2r = reinterpret_cast<const u64x2*>(sm + OFF_W2 + j * 32);
#pragma unroll
        for (int p = 0; p < 8; p++) {
            u64x2 wv = w2r[p];
            oa0[2*p]   = fma2(r0, wv.x, oa0[2*p]);
            oa0[2*p+1] = fma2(r0, wv.y, oa0[2*p+1]);
            oa1[2*p]   = fma2(r1, wv.x, oa1[2*p]);
            oa1[2*p+1] = fma2(r1, wv.y, oa1[2*p+1]);
        }
    }

    // ---- stores ----
    u64x2* or0 = reinterpret_cast<u64x2*>(out + ((size_t)b0 * TT + t) * DMM);
    u64x2* or1 = reinterpret_cast<u64x2*>(out + ((size_t)b1b * TT + t) * DMM);
#pragma unroll
    for (int p = 0; p < 8; p++) {
        or0[p] = make_ulonglong2(oa0[2*p], oa0[2*p+1]);
        or1[p] = make_ulonglong2(oa1[2*p], oa1[2*p+1]);
    }
}

extern "C" void kernel_launch(void* const* d_in, const int* in_sizes, int n_in,
                              void* d_out, int out_size) {
    const float* x   = (const float*)d_in[0];
    const float* Wq  = (const float*)d_in[1];
    const float* Wk  = (const float*)d_in[2];
    const float* Wv  = (const float*)d_in[3];
    const float* Wo  = (const float*)d_in[4];
    const float* bo  = (const float*)d_in[5];
    const float* W1  = (const float*)d_in[6];
    const float* b1  = (const float*)d_in[7];
    const float* W2  = (const float*)d_in[8];
    const float* b2  = (const float*)d_in[9];
    const float* g1  = (const float*)d_in[10];
    const float* be1 = (const float*)d_in[11];
    const float* g2  = (const float*)d_in[12];
    const float* be2 = (const float*)d_in[13];

    int B = in_sizes[0] / (TT * DMM);
    size_t shmem = SM_FLOATS * sizeof(float);
    cudaFuncSetAttribute(block_fused, cudaFuncAttributeMaxDynamicSharedMemorySize, (int)shmem);
    block_fused<<<B / 2, 128, shmem>>>(x, Wq, Wk, Wv, Wo, bo, W1, b1, W2, b2,
                                       g1, be1, g2, be2, (float*)d_out);
}

// round 7
// speedup vs baseline: 1.0928x; 1.0928x over previous
#include <cuda_runtime.h>
#include <math.h>
#include <stdint.h>

#define TT 128   // sequence length
#define DMM 32   // model dim
#define RS 36    // padded row stride (floats) for k/v smem

typedef unsigned long long u64;
typedef ulonglong2 u64x2;
typedef uint32_t u32;

// ---- packed fp32x2 primitives ----
__device__ __forceinline__ u64 fma2(u64 a, u64 b, u64 c) {
    u64 d; asm("fma.rn.f32x2 %0, %1, %2, %3;" : "=l"(d) : "l"(a), "l"(b), "l"(c)); return d;
}
__device__ __forceinline__ u64 add2(u64 a, u64 b) {
    u64 d; asm("add.rn.f32x2 %0, %1, %2;" : "=l"(d) : "l"(a), "l"(b)); return d;
}
__device__ __forceinline__ u64 mul2(u64 a, u64 b) {
    u64 d; asm("mul.rn.f32x2 %0, %1, %2;" : "=l"(d) : "l"(a), "l"(b)); return d;
}
__device__ __forceinline__ u64 pack2(float lo, float hi) {
    u64 r; asm("mov.b64 %0, {%1, %2};" : "=l"(r) : "f"(lo), "f"(hi)); return r;
}
__device__ __forceinline__ float2 unpk(u64 v) {
    float2 f; asm("mov.b64 {%0, %1}, %2;" : "=f"(f.x), "=f"(f.y) : "l"(v)); return f;
}
__device__ __forceinline__ u64 rep2(float x) { return pack2(x, x); }

// ---- tf32 helpers ----
__device__ __forceinline__ float to_tf32(float x) {
    u32 u; asm("cvt.rna.tf32.f32 %0, %1;" : "=r"(u) : "f"(x)); return __uint_as_float(u);
}
// D += A(16x8,row) * B(8x8,col); tf32 in, f32 accum
__device__ __forceinline__ void mma8(float& d0, float& d1, float& d2, float& d3,
                                     u32 a0, u32 a1, u32 a2, u32 a3, u32 b0, u32 b1) {
    asm("mma.sync.aligned.m16n8k8.row.col.f32.tf32.tf32.f32 "
        "{%0,%1,%2,%3}, {%4,%5,%6,%7}, {%8,%9}, {%0,%1,%2,%3};"
        : "+f"(d0), "+f"(d1), "+f"(d2), "+f"(d3)
        : "r"(a0), "r"(a1), "r"(a2), "r"(a3), "r"(b0), "r"(b1));
}

// ---- dynamic smem layout (float offsets) ----
#define OFF_WO   0
#define OFF_BO   1024
#define OFF_B2   1056
#define OFF_G1   1088
#define OFF_BE1  1120
#define OFF_G2   1152
#define OFF_BE2  1184
#define OFF_B1   1216
#define OFF_U    1344
// phase A (qkv + attention):
#define OFF_KS0  (OFF_U + 0)
#define OFF_VS0  (OFF_U + 4608)
#define OFF_KS1  (OFF_U + 9216)
#define OFF_VS1  (OFF_U + 13824)
#define OFF_WQ   (OFF_U + 18432)
#define OFF_WK   (OFF_U + 19456)
#define OFF_WV   (OFF_U + 20480)
#define SM_FLOATS (OFF_U + 21504)
// phase B (FFN via mma), overlays phase A:
#define OFF_ZN   (OFF_U + 0)        // [256][36] tf32 zn rows (also OS output later)
#define OFF_W1S  (OFF_U + 9216)     // [32][132] tf32
#define OFF_W2S  (OFF_U + 13440)    // [128][36] tf32
#define OFF_CHK  (OFF_U + 18048)    // 4 warps x [16][20]

// dual matvec: acc{0,1}[p] = cols(2p,2p+1) of xn{0,1}(1x32) @ w(32x32)
__device__ __forceinline__ void matvec_dual(const float* __restrict__ w,
                                            const float (&x0)[32], const float (&x1)[32],
                                            u64 (&a0)[16], u64 (&a1)[16]) {
#pragma unroll
    for (int p = 0; p < 16; p++) { a0[p] = 0ull; a1[p] = 0ull; }
#pragma unroll
    for (int d = 0; d < 32; d++) {
        u64 r0 = rep2(x0[d]), r1 = rep2(x1[d]);
        const u64x2* row = reinterpret_cast<const u64x2*>(w + d * 32);
#pragma unroll
        for (int p = 0; p < 8; p++) {
            u64x2 wv = row[p];
            a0[2*p]   = fma2(r0, wv.x, a0[2*p]);
            a0[2*p+1] = fma2(r0, wv.y, a0[2*p+1]);
            a1[2*p]   = fma2(r1, wv.x, a1[2*p]);
            a1[2*p+1] = fma2(r1, wv.y, a1[2*p+1]);
        }
    }
}

__device__ __forceinline__ void store_pairs(float* dst, const u64 (&a)[16]) {
    u64x2* d2 = reinterpret_cast<u64x2*>(dst);
#pragma unroll
    for (int p = 0; p < 8; p++) d2[p] = make_ulonglong2(a[2*p], a[2*p+1]);
}

__device__ __forceinline__ void ln32(float (&v)[32], const float* g, const float* be) {
    float mu = 0.0f;
#pragma unroll
    for (int i = 0; i < 32; i++) mu += v[i];
    mu *= (1.0f / 32.0f);
    float var = 0.0f;
#pragma unroll
    for (int i = 0; i < 32; i++) { float d = v[i] - mu; var = fmaf(d, d, var); }
    var *= (1.0f / 32.0f);
    float rstd = rsqrtf(var + 1e-5f);
#pragma unroll
    for (int i = 0; i < 32; i++) v[i] = fmaf((v[i] - mu) * rstd, g[i], be[i]);
}

__global__ void __launch_bounds__(128, 2) block_fused(
    const float* __restrict__ x,
    const float* __restrict__ Wq, const float* __restrict__ Wk, const float* __restrict__ Wv,
    const float* __restrict__ Wo, const float* __restrict__ bo,
    const float* __restrict__ W1, const float* __restrict__ b1,
    const float* __restrict__ W2, const float* __restrict__ b2,
    const float* __restrict__ g1, const float* __restrict__ be1,
    const float* __restrict__ g2, const float* __restrict__ be2,
    float* __restrict__ out)
{
    extern __shared__ float sm[];
    const int tid = threadIdx.x;
    const int t = tid;
    const int b0 = 2 * blockIdx.x, b1b = 2 * blockIdx.x + 1;

    // early x loads for both tokens
    const float4* xr0 = reinterpret_cast<const float4*>(x + ((size_t)b0 * TT + t) * DMM);
    const float4* xr1 = reinterpret_cast<const float4*>(x + ((size_t)b1b * TT + t) * DMM);
    float4 xv0[8], xv1[8];
#pragma unroll
    for (int i = 0; i < 8; i++) { xv0[i] = xr0[i]; xv1[i] = xr1[i]; }

    // ---- stage phase-A weights ----
    for (int i = tid; i < 1024; i += 128) {
        int d = i >> 5, j = i & 31;
        int kk = j >> 1, h = j & 1;            // interleaved-head columns: j = 2*kk + h
        int src = h * 512 + d * 16 + kk;
        sm[OFF_WQ + i] = Wq[src];
        sm[OFF_WK + i] = Wk[src];
        sm[OFF_WV + i] = Wv[src];
        sm[OFF_WO + i] = Wo[i];
    }
    if (tid < 32) {
        sm[OFF_BO  + tid] = bo[tid];  sm[OFF_B2  + tid] = b2[tid];
        sm[OFF_G1  + tid] = g1[tid];  sm[OFF_BE1 + tid] = be1[tid];
        sm[OFF_G2  + tid] = g2[tid];  sm[OFF_BE2 + tid] = be2[tid];
    }
    sm[OFF_B1 + tid] = b1[tid];
    __syncthreads();

    // ---- LN1 for both tokens ----
    float xn0[32], xn1[32];
#pragma unroll
    for (int i = 0; i < 8; i++) {
        xn0[4*i+0] = xv0[i].x; xn0[4*i+1] = xv0[i].y; xn0[4*i+2] = xv0[i].z; xn0[4*i+3] = xv0[i].w;
        xn1[4*i+0] = xv1[i].x; xn1[4*i+1] = xv1[i].y; xn1[4*i+2] = xv1[i].z; xn1[4*i+3] = xv1[i].w;
    }
    ln32(xn0, sm + OFF_G1, sm + OFF_BE1);
    ln32(xn1, sm + OFF_G1, sm + OFF_BE1);

    // ---- q,k,v projections (dual): k,v -> smem; q in regs ----
    u64 qp0[16], qp1[16];
    {
        u64 a0[16], a1[16];
        matvec_dual(sm + OFF_WK, xn0, xn1, a0, a1);
        store_pairs(sm + OFF_KS0 + t * RS, a0);
        store_pairs(sm + OFF_KS1 + t * RS, a1);
        matvec_dual(sm + OFF_WV, xn0, xn1, a0, a1);
        store_pairs(sm + OFF_VS0 + t * RS, a0);
        store_pairs(sm + OFF_VS1 + t * RS, a1);
        matvec_dual(sm + OFF_WQ, xn0, xn1, qp0, qp1);
    }
    __syncthreads();

    // ---- causal attention, both batches, both heads per f32x2 pair ----
    u64 av0[16], av1[16];
#pragma unroll
    for (int c = 0; c < 16; c++) { av0[c] = 0ull; av1[c] = 0ull; }
    float l00 = 0.0f, l01 = 0.0f, l10 = 0.0f, l11 = 0.0f;
    for (int si = 0; si <= t; si++) {
        const u64x2* kr0 = reinterpret_cast<const u64x2*>(sm + OFF_KS0 + si * RS);
        const u64x2* kr1 = reinterpret_cast<const u64x2*>(sm + OFF_KS1 + si * RS);
        u64 s0 = 0ull, s1 = 0ull, s2 = 0ull, s3 = 0ull;
        u64 u0 = 0ull, u1 = 0ull, u2 = 0ull, u3 = 0ull;
#pragma unroll
        for (int p = 0; p < 4; p++) {
            u64x2 ka = kr0[2*p], kb = kr0[2*p+1];
            s0 = fma2(qp0[4*p+0], ka.x, s0); s1 = fma2(qp0[4*p+1], ka.y, s1);
            s2 = fma2(qp0[4*p+2], kb.x, s2); s3 = fma2(qp0[4*p+3], kb.y, s3);
            u64x2 kc = kr1[2*p], kd = kr1[2*p+1];
            u0 = fma2(qp1[4*p+0], kc.x, u0); u1 = fma2(qp1[4*p+1], kc.y, u1);
            u2 = fma2(qp1[4*p+2], kd.x, u2); u3 = fma2(qp1[4*p+3], kd.y, u3);
        }
        float2 sa = unpk(add2(add2(s0, s1), add2(s2, s3)));   // (h0,h1) batch0
        float2 sb = unpk(add2(add2(u0, u1), add2(u2, u3)));   // (h0,h1) batch1
        float p00 = __expf(sa.x), p01 = __expf(sa.y);         // |score| <~ 8, no max-sub
        float p10 = __expf(sb.x), p11 = __expf(sb.y);
        l00 += p00; l01 += p01; l10 += p10; l11 += p11;
        u64 pa = pack2(p00, p01), pb = pack2(p10, p11);
        const u64x2* vr0 = reinterpret_cast<const u64x2*>(sm + OFF_VS0 + si * RS);
        const u64x2* vr1 = reinterpret_cast<const u64x2*>(sm + OFF_VS1 + si * RS);
#pragma unroll
        for (int p = 0; p < 8; p++) {
            u64x2 va = vr0[p];
            av0[2*p]   = fma2(pa, va.x, av0[2*p]);
            av0[2*p+1] = fma2(pa, va.y, av0[2*p+1]);
            u64x2 vb = vr1[p];
            av1[2*p]   = fma2(pb, vb.x, av1[2*p]);
            av1[2*p+1] = fma2(pb, vb.y, av1[2*p+1]);
        }
    }
    float at0[32], at1[32];   // standard order: at[h*16+c]
    {
        u64 ia = pack2(__fdividef(1.0f, l00), __fdividef(1.0f, l01));
        u64 ib = pack2(__fdividef(1.0f, l10), __fdividef(1.0f, l11));
#pragma unroll
        for (int c = 0; c < 16; c++) {
            float2 a = unpk(mul2(av0[c], ia));
            at0[c] = a.x; at0[16 + c] = a.y;
            float2 b = unpk(mul2(av1[c], ib));
            at1[c] = b.x; at1[16 + c] = b.y;
        }
    }

    // ---- output projection + residual (dual, scalar) ----
    float z0[32], z1[32];
    {
        u64 o0[16], o1[16];
#pragma unroll
        for (int p = 0; p < 16; p++) { o0[p] = 0ull; o1[p] = 0ull; }
#pragma unroll
        for (int j = 0; j < 32; j++) {
            u64 a0 = rep2(at0[j]), a1 = rep2(at1[j]);
            const u64x2* row = reinterpret_cast<const u64x2*>(sm + OFF_WO + j * 32);
#pragma unroll
            for (int p = 0; p < 8; p++) {
                u64x2 wv = row[p];
                o0[2*p]   = fma2(a0, wv.x, o0[2*p]);
                o0[2*p+1] = fma2(a0, wv.y, o0[2*p+1]);
                o1[2*p]   = fma2(a1, wv.x, o1[2*p]);
                o1[2*p+1] = fma2(a1, wv.y, o1[2*p+1]);
            }
        }
#pragma unroll
        for (int p = 0; p < 16; p++) {
            float2 a = unpk(o0[p]);
            z0[2*p]   = xn0[2*p]   + a.x + sm[OFF_BO + 2*p];
            z0[2*p+1] = xn0[2*p+1] + a.y + sm[OFF_BO + 2*p+1];
            float2 b = unpk(o1[p]);
            z1[2*p]   = xn1[2*p]   + b.x + sm[OFF_BO + 2*p];
            z1[2*p+1] = xn1[2*p+1] + b.y + sm[OFF_BO + 2*p+1];
        }
    }

    // ---- LN2 (z0/z1 become zn; kept in regs for final residual) ----
    ln32(z0, sm + OFF_G2, sm + OFF_BE2);
    ln32(z1, sm + OFF_G2, sm + OFF_BE2);

    // ================= FFN via tf32 mma.sync =================
    __syncthreads();   // phase-A smem (union region) now dead

    // stage W1 [32][128] -> [32][132] tf32 ; W2 [128][32] -> [128][36] tf32
    for (int i = tid; i < 4096; i += 128) {
        sm[OFF_W1S + (i >> 7) * 132 + (i & 127)] = to_tf32(W1[i]);
        sm[OFF_W2S + (i >> 5) * 36  + (i & 31)]  = to_tf32(W2[i]);
    }
    // write zn rows (tf32) — row t = batch0, row 128+t = batch1
    {
        float4* zr0 = reinterpret_cast<float4*>(sm + OFF_ZN + t * 36);
        float4* zr1 = reinterpret_cast<float4*>(sm + OFF_ZN + (128 + t) * 36);
#pragma unroll
        for (int c4 = 0; c4 < 8; c4++) {
            zr0[c4] = make_float4(to_tf32(z0[4*c4+0]), to_tf32(z0[4*c4+1]),
                                  to_tf32(z0[4*c4+2]), to_tf32(z0[4*c4+3]));
            zr1[c4] = make_float4(to_tf32(z1[4*c4+0]), to_tf32(z1[4*c4+1]),
                                  to_tf32(z1[4*c4+2]), to_tf32(z1[4*c4+3]));
        }
    }
    __syncthreads();

    const int lam = tid & 31, wid4 = tid >> 5;
    const int lr = lam >> 2, lc = lam & 3;
    const float* zb  = sm + OFF_ZN;
    const float* w1s = sm + OFF_W1S;
    const float* w2s = sm + OFF_W2S;
    float* ck = sm + OFF_CHK + wid4 * 320;   // per-warp [16][20] chunk

    float c2[4][4][4];
#pragma unroll
    for (int a = 0; a < 4; a++)
#pragma unroll
        for (int b = 0; b < 4; b++)
#pragma unroll
            for (int c = 0; c < 4; c++) c2[a][b][c] = 0.0f;

#pragma unroll
    for (int rtl = 0; rtl < 4; rtl++) {
        const int rb = wid4 * 64 + rtl * 16;
        // A fragments for this 16-row tile (all 4 k-tiles), held in regs
        u32 A[4][4];
#pragma unroll
        for (int kt = 0; kt < 4; kt++) {
            A[kt][0] = __float_as_uint(zb[(rb + lr)     * 36 + lc     + 8*kt]);
            A[kt][1] = __float_as_uint(zb[(rb + lr + 8) * 36 + lc     + 8*kt]);
            A[kt][2] = __float_as_uint(zb[(rb + lr)     * 36 + lc + 4 + 8*kt]);
            A[kt][3] = __float_as_uint(zb[(rb + lr + 8) * 36 + lc + 4 + 8*kt]);
        }
#pragma unroll
        for (int g = 0; g < 8; g++) {
            // FFN1: 16 hidden cols (n-tiles 2g, 2g+1), bias+relu, to chunk (tf32)
#pragma unroll
            for (int ntl = 0; ntl < 2; ntl++) {
                const int nt = 2*g + ntl;
                float h0 = 0.f, h1 = 0.f, h2 = 0.f, h3 = 0.f;
#pragma unroll
                for (int kt = 0; kt < 4; kt++) {
                    u32 wb0 = __float_as_uint(w1s[(lc     + 8*kt) * 132 + lr + 8*nt]);
                    u32 wb1 = __float_as_uint(w1s[(lc + 4 + 8*kt) * 132 + lr + 8*nt]);
                    mma8(h0, h1, h2, h3, A[kt][0], A[kt][1], A[kt][2], A[kt][3], wb0, wb1);
                }
                const float bj0 = sm[OFF_B1 + 8*nt + 2*lc];
                const float bj1 = sm[OFF_B1 + 8*nt + 2*lc + 1];
                h0 = fmaxf(h0 + bj0, 0.f); h1 = fmaxf(h1 + bj1, 0.f);
                h2 = fmaxf(h2 + bj0, 0.f); h3 = fmaxf(h3 + bj1, 0.f);
                *reinterpret_cast<float2*>(ck + lr * 20       + 2*lc + 8*ntl) =
                    make_float2(to_tf32(h0), to_tf32(h1));
                *reinterpret_cast<float2*>(ck + (lr + 8) * 20 + 2*lc + 8*ntl) =
                    make_float2(to_tf32(h2), to_tf32(h3));
            }
            __syncwarp();
            // FFN2 partial over these 16 hidden cols, accumulate in frags
#pragma unroll
            for (int ktl = 0; ktl < 2; ktl++) {
                u32 p0 = __float_as_uint(ck[lr * 20       + lc     + 8*ktl]);
                u32 p1 = __float_as_uint(ck[(lr + 8) * 20 + lc     + 8*ktl]);
                u32 p2 = __float_as_uint(ck[lr * 20       + lc + 4 + 8*ktl]);
                u32 p3 = __float_as_uint(ck[(lr + 8) * 20 + lc + 4 + 8*ktl]);
                const int ktg = 2*g + ktl;
#pragma unroll
                for (int nt2 = 0; nt2 < 4; nt2++) {
                    u32 wb0 = __float_as_uint(w2s[(lc     + 8*ktg) * 36 + lr + 8*nt2]);
                    u32 wb1 = __float_as_uint(w2s[(lc + 4 + 8*ktg) * 36 + lr + 8*nt2]);
                    mma8(c2[rtl][nt2][0], c2[rtl][nt2][1], c2[rtl][nt2][2], c2[rtl][nt2][3],
                         p0, p1, p2, p3, wb0, wb1);
                }
            }
            __syncwarp();
        }
    }

    // scatter C2 fragments to smem (overlay ZN, now dead), then final add + store
    __syncthreads();
    float* os = sm + OFF_ZN;
#pragma unroll
    for (int rtl = 0; rtl < 4; rtl++) {
        const int rb = wid4 * 64 + rtl * 16;
#pragma unroll
        for (int nt2 = 0; nt2 < 4; nt2++) {
            *reinterpret_cast<float2*>(os + (rb + lr)     * 36 + 8*nt2 + 2*lc) =
                make_float2(c2[rtl][nt2][0], c2[rtl][nt2][1]);
            *reinterpret_cast<float2*>(os + (rb + lr + 8) * 36 + 8*nt2 + 2*lc) =
                make_float2(c2[rtl][nt2][2], c2[rtl][nt2][3]);
        }
    }
    __syncthreads();

    {
        const float* r0 = os + t * 36;
        const float* r1 = os + (128 + t) * 36;
        float4* o0 = reinterpret_cast<float4*>(out + ((size_t)b0  * TT + t) * DMM);
        float4* o1 = reinterpret_cast<float4*>(out + ((size_t)b1b * TT + t) * DMM);
#pragma unroll
        for (int c4 = 0; c4 < 8; c4++) {
            o0[c4] = make_float4(z0[4*c4+0] + r0[4*c4+0] + sm[OFF_B2 + 4*c4+0],
                                 z0[4*c4+1] + r0[4*c4+1] + sm[OFF_B2 + 4*c4+1],
                                 z0[4*c4+2] + r0[4*c4+2] + sm[OFF_B2 + 4*c4+2],
                                 z0[4*c4+3] + r0[4*c4+3] + sm[OFF_B2 + 4*c4+3]);
            o1[c4] = make_float4(z1[4*c4+0] + r1[4*c4+0] + sm[OFF_B2 + 4*c4+0],
                                 z1[4*c4+1] + r1[4*c4+1] + sm[OFF_B2 + 4*c4+1],
                                 z1[4*c4+2] + r1[4*c4+2] + sm[OFF_B2 + 4*c4+2],
                                 z1[4*c4+3] + r1[4*c4+3] + sm[OFF_B2 + 4*c4+3]);
        }
    }
}

extern "C" void kernel_launch(void* const* d_in, const int* in_sizes, int n_in,
                              void* d_out, int out_size) {
    const float* x   = (const float*)d_in[0];
    const float* Wq  = (const float*)d_in[1];
    const float* Wk  = (const float*)d_in[2];
    const float* Wv  = (const float*)d_in[3];
    const float* Wo  = (const float*)d_in[4];
    const float* bo  = (const float*)d_in[5];
    const float* W1  = (const float*)d_in[6];
    const float* b1  = (const float*)d_in[7];
    const float* W2  = (const float*)d_in[8];
    const float* b2  = (const float*)d_in[9];
    const float* g1  = (const float*)d_in[10];
    const float* be1 = (const float*)d_in[11];
    const float* g2  = (const float*)d_in[12];
    const float* be2 = (const float*)d_in[13];

    int B = in_sizes[0] / (TT * DMM);
    size_t shmem = SM_FLOATS * sizeof(float);
    cudaFuncSetAttribute(block_fused, cudaFuncAttributeMaxDynamicSharedMemorySize, (int)shmem);
    block_fused<<<B / 2, 128, shmem>>>(x, Wq, Wk, Wv, Wo, bo, W1, b1, W2, b2,
                                       g1, be1, g2, be2, (float*)d_out);
}